// round 14
// baseline (speedup 1.0000x reference)
#include <cuda_runtime.h>
#include <cstddef>

#define TPB 32               // one warp per CTA
#define STRIDE 62            // floats per smem row (max stage chunk 60); 62 == 2 mod 4
                             // => 64-bit smem ops conflict-free (bank-pair stride 31, odd)

static constexpr int NB = 131072;

// ---------------------------------------------------------------------------
// Compile-time Clebsch-Gordan coefficients (Racah formula), double precision,
// evaluated entirely by the compiler (constexpr Newton sqrt).
// ---------------------------------------------------------------------------
__host__ __device__ constexpr double factd(int n) {
    double r = 1.0;
    for (int i = 2; i <= n; ++i) r *= (double)i;
    return r;
}
__host__ __device__ constexpr double csqrt(double x) {
    if (x <= 0.0) return 0.0;
    double g = x > 1.0 ? x : 1.0;
    for (int i = 0; i < 100; ++i) g = 0.5 * (g + x / g);
    return g;
}
__host__ __device__ constexpr int iabs_c(int x) { return x < 0 ? -x : x; }
__host__ __device__ constexpr int imin6(int a, int b, int c, int d, int e, int f) {
    int m = a;
    if (b < m) m = b; if (c < m) m = c; if (d < m) m = d;
    if (e < m) m = e; if (f < m) m = f;
    return m;
}

__host__ __device__ constexpr double cgco(int j1, int m1, int j2, int m2, int j, int m) {
    if (m1 + m2 != m) return 0.0;
    if (j < iabs_c(j1 - j2) || j > j1 + j2) return 0.0;
    if (iabs_c(m) > j || iabs_c(m1) > j1 || iabs_c(m2) > j2) return 0.0;
    double pre = csqrt((2.0 * j + 1.0) * factd(j1 + j2 - j) * factd(j + j1 - j2) *
                       factd(j + j2 - j1) / factd(j1 + j2 + j + 1));
    pre *= csqrt(factd(j + m) * factd(j - m) * factd(j1 + m1) * factd(j1 - m1) *
                 factd(j2 + m2) * factd(j2 - m2));
    double s = 0.0;
    for (int k = 0; k <= j1 + j2 - j; ++k) {
        const int d1 = k;
        const int d2 = j1 + j2 - j - k;
        const int d3 = j1 - m1 - k;
        const int d4 = j2 + m2 - k;
        const int d5 = j - j2 + m1 + k;
        const int d6 = j - j1 - m2 + k;
        if (imin6(d1, d2, d3, d4, d5, d6) < 0) continue;
        const double denom = factd(d1) * factd(d2) * factd(d3) * factd(d4) * factd(d5) * factd(d6);
        s += ((k & 1) ? -1.0 : 1.0) / denom;
    }
    return pre * s;
}

// Register-array offset for input part l (sizes 1,3,5,7 -> offsets 0,1,4,9)
template <int L>
__host__ __device__ constexpr int xoff() { return L == 0 ? 0 : (L == 1 ? 1 : (L == 2 ? 4 : 9)); }

// ---------------------------------------------------------------------------
// Template-unrolled accumulation: sum over m1 for one (l1,l2,l,m) entry set.
// All CG coefficients become FFMA immediates; zero coefficients pruned.
// ---------------------------------------------------------------------------
template <int L1, int L2, int L, int M, int M1>
__device__ __forceinline__ void acc_m1(float& fr, float& fi, const float* xr, const float* xi) {
    constexpr int M2 = M - M1;
    if constexpr (M2 >= -L2 && M2 <= L2) {
        constexpr double Cd = cgco(L1, M1, L2, M2, L, M);
        if constexpr (Cd != 0.0) {
            constexpr float C = (float)Cd;
            const float a = xr[xoff<L1>() + M1 + L1];
            const float b = xi[xoff<L1>() + M1 + L1];
            const float c = xr[xoff<L2>() + M2 + L2];
            const float d = xi[xoff<L2>() + M2 + L2];
            const float pr = fmaf(-b, d, a * c);   // Re(x*y)
            const float pi = fmaf( b, c, a * d);   // Im(x*y)
            fr = fmaf(C, pr, fr);
            fi = fmaf(C, pi, fi);
        }
    }
    if constexpr (M1 < L1) acc_m1<L1, L2, L, M, M1 + 1>(fr, fi, xr, xi);
}

// Diagonal fragment (l1==l2): compute once, one float2 STS at POS (even).
template <int POS, int L, int L1, int L2, int M>
__device__ __forceinline__ void frag1(float* row, const float* xr, const float* xi) {
    float fr = 0.0f, fi = 0.0f;
    acc_m1<L1, L2, L, M, (-L1)>(fr, fi, xr, xi);
    *reinterpret_cast<float2*>(row + POS) = make_float2(fr, fi);
}

// Off-diagonal pair: CG symmetry <l2 m2 l1 m1|l m> = (-1)^(l1+l2-l) <l1 m1 l2 m2|l m>
// and commutativity of the complex product give frag_(l2,l1) = SGN*frag_(l1,l2)
// EXACTLY (bit-identical). Compute once, store both slots.
template <int POS1, int POS2, int SGN, int L, int L1, int L2, int M>
__device__ __forceinline__ void frag2(float* row, const float* xr, const float* xi) {
    float fr = 0.0f, fi = 0.0f;
    acc_m1<L1, L2, L, M, (-L1)>(fr, fi, xr, xi);
    *reinterpret_cast<float2*>(row + POS1) = make_float2(fr, fi);
    *reinterpret_cast<float2*>(row + POS2) =
        make_float2((float)SGN * fr, (float)SGN * fi);
}

// Warp store of one CHUNK-float stage for 32 elements. Division-free affine
// addressing: lane j (< CHUNK/2) stores float2 #j of element e; loop over e.
template <int CHUNK, int OFF>
__device__ __forceinline__ void store_stage(const float* smw, float* __restrict__ out,
                                            int wbase, int lane) {
    __syncwarp();
    constexpr int C2 = CHUNK / 2;
    if (lane < C2) {
        const float* src = smw + 2 * lane;
        float* dst = out + (size_t)wbase * 512 + OFF + 2 * lane;
        #pragma unroll 8
        for (int e = 0; e < 32; ++e) {
            const float2 v = *reinterpret_cast<const float2*>(src + e * STRIDE);
            *reinterpret_cast<float2*>(dst + (size_t)e * 512) = v;
        }
    }
    __syncwarp();
}

#define F1(POS, L, L1, L2, M) frag1<POS, L, L1, L2, M>(row, xr, xi);
#define F2(P1, P2, S, L, L1, L2, M) frag2<P1, P2, S, L, L1, L2, M>(row, xr, xi);

// m-run emitters: all fragments of output part L at one m, at run-relative
// float position POS + 2*FI. Fragment order = gelib (l1 outer). Off-diagonal
// partners share one computation (signs from (-1)^(l1+l2-l)).
#define L0RUN(POS)                                                          \
    F1(POS + 0, 0, 0, 0, 0) F1(POS + 2, 0, 1, 1, 0)                         \
    F1(POS + 4, 0, 2, 2, 0) F1(POS + 6, 0, 3, 3, 0)
#define L1RUN(POS, M)  /* FIs: (0,1)0 (1,0)1 (1,1)2 (1,2)3 (2,1)4 (2,2)5 (2,3)6 (3,2)7 (3,3)8 */ \
    F2(POS + 0,  POS + 2,  +1, 1, 0, 1, M)                                  \
    F1(POS + 4,  1, 1, 1, M)                                                \
    F2(POS + 6,  POS + 8,  +1, 1, 1, 2, M)                                  \
    F1(POS + 10, 1, 2, 2, M)                                                \
    F2(POS + 12, POS + 14, +1, 1, 2, 3, M)                                  \
    F1(POS + 16, 1, 3, 3, M)
#define L2RUN(POS, M)  /* (0,2)0 (1,1)1 (1,2)2 (1,3)3 (2,0)4 (2,1)5 (2,2)6 (2,3)7 (3,1)8 (3,2)9 (3,3)10 */ \
    F2(POS + 0,  POS + 8,  +1, 2, 0, 2, M)                                  \
    F1(POS + 2,  2, 1, 1, M)                                                \
    F2(POS + 4,  POS + 10, -1, 2, 1, 2, M)                                  \
    F2(POS + 6,  POS + 16, +1, 2, 1, 3, M)                                  \
    F1(POS + 12, 2, 2, 2, M)                                                \
    F2(POS + 14, POS + 18, -1, 2, 2, 3, M)                                  \
    F1(POS + 20, 2, 3, 3, M)
#define L3RUN(POS, M)  /* (0,3)0 (1,2)1 (1,3)2 (2,1)3 (2,2)4 (2,3)5 (3,0)6 (3,1)7 (3,2)8 (3,3)9 */ \
    F2(POS + 0,  POS + 12, +1, 3, 0, 3, M)                                  \
    F2(POS + 2,  POS + 6,  +1, 3, 1, 2, M)                                  \
    F2(POS + 4,  POS + 14, -1, 3, 1, 3, M)                                  \
    F1(POS + 8,  3, 2, 2, M)                                                \
    F2(POS + 10, POS + 16, +1, 3, 2, 3, M)                                  \
    F1(POS + 18, 3, 3, 3, M)
#define L4RUN(POS, M)  /* (1,3)0 (2,2)1 (2,3)2 (3,1)3 (3,2)4 (3,3)5 */      \
    F2(POS + 0, POS + 6, +1, 4, 1, 3, M)                                    \
    F1(POS + 2, 4, 2, 2, M)                                                 \
    F2(POS + 4, POS + 8, -1, 4, 2, 3, M)                                    \
    F1(POS + 10, 4, 3, 3, M)
#define L5RUN(POS, M)  /* (2,3)0 (3,2)1 (3,3)2 */                           \
    F2(POS + 0, POS + 2, +1, 5, 2, 3, M)                                    \
    F1(POS + 4, 5, 3, 3, M)

// ---------------------------------------------------------------------------
// Main kernel: one warp per CTA, one thread per batch element; warp-private
// smem staging. 10 stages split ONLY at m-run boundaries so every off-diag
// partner pair stays in one stage (chunks 44/40/44/44/60/60/56/60/60/44).
// Occupancy step: 18 CTAs/SM => 113-reg cap (controlled +12.5% warps vs the
// proven 128-reg config; R13's symmetry-shared fragments lowered live
// pressure, so minor headroom loss should not spill).
// Output layout per element (512 floats):
//   l=0 @0(8)  l=1 @8(54)  l=2 @62(110)  l=3 @172(140)
//   l=4 @312(108)  l=5 @420(66)  l=6 @486(26)
// ---------------------------------------------------------------------------
__global__ void __launch_bounds__(TPB, 18)
cgprod_kernel(const float* __restrict__ x0, const float* __restrict__ x1,
              const float* __restrict__ x2, const float* __restrict__ x3,
              float* __restrict__ out) {
    __shared__ float sm[32 * STRIDE];   // 7936 B per CTA (18 CTAs = 143 KB/SM)
    const int lane  = threadIdx.x & 31;
    const int wbase = blockIdx.x * 32;
    const int b     = wbase + lane;

    float xr[16], xi[16];
    {
        const float2 v = reinterpret_cast<const float2*>(x0)[b];
        xr[0] = v.x; xi[0] = v.y;
    }
    {
        const float2* p = reinterpret_cast<const float2*>(x1) + (size_t)b * 3;
        #pragma unroll
        for (int k = 0; k < 3; ++k) { const float2 v = p[k]; xr[1 + k] = v.x; xi[1 + k] = v.y; }
    }
    {
        const float2* p = reinterpret_cast<const float2*>(x2) + (size_t)b * 5;
        #pragma unroll
        for (int k = 0; k < 5; ++k) { const float2 v = p[k]; xr[4 + k] = v.x; xi[4 + k] = v.y; }
    }
    {
        const float2* p = reinterpret_cast<const float2*>(x3) + (size_t)b * 7;
        #pragma unroll
        for (int k = 0; k < 7; ++k) { const float2 v = p[k]; xr[9 + k] = v.x; xi[9 + k] = v.y; }
    }

    float* row = sm + lane * STRIDE;    // this lane's staging row

    // Stage 0 @0 (44): l0 | l1 m=-1 | l1 m=0
    { L0RUN(0) L1RUN(8, -1) L1RUN(26, 0) }
    store_stage<44, 0>(sm, out, wbase, lane);

    // Stage 1 @44 (40): l1 m=1 | l2 m=-2
    { L1RUN(0, 1) L2RUN(18, -2) }
    store_stage<40, 44>(sm, out, wbase, lane);

    // Stage 2 @84 (44): l2 m=-1 | l2 m=0
    { L2RUN(0, -1) L2RUN(22, 0) }
    store_stage<44, 84>(sm, out, wbase, lane);

    // Stage 3 @128 (44): l2 m=1 | l2 m=2
    { L2RUN(0, 1) L2RUN(22, 2) }
    store_stage<44, 128>(sm, out, wbase, lane);

    // Stage 4 @172 (60): l3 m=-3,-2,-1
    { L3RUN(0, -3) L3RUN(20, -2) L3RUN(40, -1) }
    store_stage<60, 172>(sm, out, wbase, lane);

    // Stage 5 @232 (60): l3 m=0,1,2
    { L3RUN(0, 0) L3RUN(20, 1) L3RUN(40, 2) }
    store_stage<60, 232>(sm, out, wbase, lane);

    // Stage 6 @292 (56): l3 m=3 | l4 m=-4,-3,-2
    { L3RUN(0, 3) L4RUN(20, -4) L4RUN(32, -3) L4RUN(44, -2) }
    store_stage<56, 292>(sm, out, wbase, lane);

    // Stage 7 @348 (60): l4 m=-1,0,1,2,3
    { L4RUN(0, -1) L4RUN(12, 0) L4RUN(24, 1) L4RUN(36, 2) L4RUN(48, 3) }
    store_stage<60, 348>(sm, out, wbase, lane);

    // Stage 8 @408 (60): l4 m=4 | l5 m=-5..2
    {
        L4RUN(0, 4)
        L5RUN(12, -5) L5RUN(18, -4) L5RUN(24, -3) L5RUN(30, -2)
        L5RUN(36, -1) L5RUN(42, 0)  L5RUN(48, 1)  L5RUN(54, 2)
    }
    store_stage<60, 408>(sm, out, wbase, lane);

    // Stage 9 @468 (44): l5 m=3,4,5 | l6 m=-6..6
    {
        L5RUN(0, 3) L5RUN(6, 4) L5RUN(12, 5)
        F1(18, 6, 3, 3, -6) F1(20, 6, 3, 3, -5) F1(22, 6, 3, 3, -4)
        F1(24, 6, 3, 3, -3) F1(26, 6, 3, 3, -2) F1(28, 6, 3, 3, -1)
        F1(30, 6, 3, 3,  0) F1(32, 6, 3, 3,  1) F1(34, 6, 3, 3,  2)
        F1(36, 6, 3, 3,  3) F1(38, 6, 3, 3,  4) F1(40, 6, 3, 3,  5)
        F1(42, 6, 3, 3,  6)
    }
    store_stage<44, 468>(sm, out, wbase, lane);
}

extern "C" void kernel_launch(void* const* d_in, const int* in_sizes, int n_in,
                              void* d_out, int out_size) {
    // Defensive: map inputs by element count (all four are distinct).
    const float* xp[4] = {nullptr, nullptr, nullptr, nullptr};
    for (int i = 0; i < n_in && i < 8; ++i) {
        const int s = in_sizes[i];
        if      (s == NB * 2)  xp[0] = (const float*)d_in[i];
        else if (s == NB * 6)  xp[1] = (const float*)d_in[i];
        else if (s == NB * 10) xp[2] = (const float*)d_in[i];
        else if (s == NB * 14) xp[3] = (const float*)d_in[i];
    }
    cgprod_kernel<<<NB / TPB, TPB>>>(xp[0], xp[1], xp[2], xp[3], (float*)d_out);
}

// round 15
// speedup vs baseline: 1.1724x; 1.1724x over previous
#include <cuda_runtime.h>
#include <cstddef>

#define TPB 32               // one warp per CTA
#define STRIDE 54            // floats per smem row (max stage chunk 52);
                             // 216B row = 27 bank-pairs (odd) -> conflict-free STS.64

static constexpr int NB = 131072;

// ---------------------------------------------------------------------------
// Compile-time Clebsch-Gordan coefficients (Racah formula), double precision,
// evaluated entirely by the compiler (constexpr Newton sqrt).
// ---------------------------------------------------------------------------
__host__ __device__ constexpr double factd(int n) {
    double r = 1.0;
    for (int i = 2; i <= n; ++i) r *= (double)i;
    return r;
}
__host__ __device__ constexpr double csqrt(double x) {
    if (x <= 0.0) return 0.0;
    double g = x > 1.0 ? x : 1.0;
    for (int i = 0; i < 100; ++i) g = 0.5 * (g + x / g);
    return g;
}
__host__ __device__ constexpr int iabs_c(int x) { return x < 0 ? -x : x; }
__host__ __device__ constexpr int imin6(int a, int b, int c, int d, int e, int f) {
    int m = a;
    if (b < m) m = b; if (c < m) m = c; if (d < m) m = d;
    if (e < m) m = e; if (f < m) m = f;
    return m;
}

__host__ __device__ constexpr double cgco(int j1, int m1, int j2, int m2, int j, int m) {
    if (m1 + m2 != m) return 0.0;
    if (j < iabs_c(j1 - j2) || j > j1 + j2) return 0.0;
    if (iabs_c(m) > j || iabs_c(m1) > j1 || iabs_c(m2) > j2) return 0.0;
    double pre = csqrt((2.0 * j + 1.0) * factd(j1 + j2 - j) * factd(j + j1 - j2) *
                       factd(j + j2 - j1) / factd(j1 + j2 + j + 1));
    pre *= csqrt(factd(j + m) * factd(j - m) * factd(j1 + m1) * factd(j1 - m1) *
                 factd(j2 + m2) * factd(j2 - m2));
    double s = 0.0;
    for (int k = 0; k <= j1 + j2 - j; ++k) {
        const int d1 = k;
        const int d2 = j1 + j2 - j - k;
        const int d3 = j1 - m1 - k;
        const int d4 = j2 + m2 - k;
        const int d5 = j - j2 + m1 + k;
        const int d6 = j - j1 - m2 + k;
        if (imin6(d1, d2, d3, d4, d5, d6) < 0) continue;
        const double denom = factd(d1) * factd(d2) * factd(d3) * factd(d4) * factd(d5) * factd(d6);
        s += ((k & 1) ? -1.0 : 1.0) / denom;
    }
    return pre * s;
}

// Register-array offset for input part l (sizes 1,3,5,7 -> offsets 0,1,4,9)
template <int L>
__host__ __device__ constexpr int xoff() { return L == 0 ? 0 : (L == 1 ? 1 : (L == 2 ? 4 : 9)); }

// ---------------------------------------------------------------------------
// Template-unrolled accumulation: sum over m1 for one (l1,l2,l,m) entry set.
// All CG coefficients become FFMA immediates; zero coefficients pruned.
// ---------------------------------------------------------------------------
template <int L1, int L2, int L, int M, int M1>
__device__ __forceinline__ void acc_m1(float& fr, float& fi, const float* xr, const float* xi) {
    constexpr int M2 = M - M1;
    if constexpr (M2 >= -L2 && M2 <= L2) {
        constexpr double Cd = cgco(L1, M1, L2, M2, L, M);
        if constexpr (Cd != 0.0) {
            constexpr float C = (float)Cd;
            const float a = xr[xoff<L1>() + M1 + L1];
            const float b = xi[xoff<L1>() + M1 + L1];
            const float c = xr[xoff<L2>() + M2 + L2];
            const float d = xi[xoff<L2>() + M2 + L2];
            const float pr = fmaf(-b, d, a * c);   // Re(x*y)
            const float pi = fmaf( b, c, a * d);   // Im(x*y)
            fr = fmaf(C, pr, fr);
            fi = fmaf(C, pi, fi);
        }
    }
    if constexpr (M1 < L1) acc_m1<L1, L2, L, M, M1 + 1>(fr, fi, xr, xi);
}

// Diagonal fragment (l1==l2): compute once, one float2 STS at POS (even).
template <int POS, int L, int L1, int L2, int M>
__device__ __forceinline__ void frag1(float* row, const float* xr, const float* xi) {
    float fr = 0.0f, fi = 0.0f;
    acc_m1<L1, L2, L, M, (-L1)>(fr, fi, xr, xi);
    *reinterpret_cast<float2*>(row + POS) = make_float2(fr, fi);
}

// Off-diagonal pair: CG symmetry <l2 m2 l1 m1|l m> = (-1)^(l1+l2-l) <l1 m1 l2 m2|l m>
// and commutativity of the complex product give frag_(l2,l1) = SGN*frag_(l1,l2)
// EXACTLY (bit-identical). Compute once, store both slots.
template <int POS1, int POS2, int SGN, int L, int L1, int L2, int M>
__device__ __forceinline__ void frag2(float* row, const float* xr, const float* xi) {
    float fr = 0.0f, fi = 0.0f;
    acc_m1<L1, L2, L, M, (-L1)>(fr, fi, xr, xi);
    *reinterpret_cast<float2*>(row + POS1) = make_float2(fr, fi);
    *reinterpret_cast<float2*>(row + POS2) =
        make_float2((float)SGN * fr, (float)SGN * fi);
}

// Warp store of one CHUNK-float stage for 32 elements from buffer `buf`.
// Division-free affine addressing: lane j (< CHUNK/2) stores float2 #j of
// element e. NOTE: no trailing syncwarp — the next stage writes the OTHER
// buffer; WAR on this buffer is protected by the following stage's syncwarp.
// unroll 4 leaves scheduler room to interleave next-stage FFMAs with STGs.
template <int CHUNK, int OFF>
__device__ __forceinline__ void store_stage(const float* buf, float* __restrict__ out,
                                            int wbase, int lane) {
    __syncwarp();
    constexpr int C2 = CHUNK / 2;
    if (lane < C2) {
        const float* src = buf + 2 * lane;
        float* dst = out + (size_t)wbase * 512 + OFF + 2 * lane;
        #pragma unroll 4
        for (int e = 0; e < 32; ++e) {
            const float2 v = *reinterpret_cast<const float2*>(src + e * STRIDE);
            *reinterpret_cast<float2*>(dst + (size_t)e * 512) = v;
        }
    }
}

#define F1(POS, L, L1, L2, M) frag1<POS, L, L1, L2, M>(row, xr, xi);
#define F2(P1, P2, S, L, L1, L2, M) frag2<P1, P2, S, L, L1, L2, M>(row, xr, xi);

// m-run emitters: all fragments of output part L at one m, at run-relative
// float position POS + 2*FI. Fragment order = gelib (l1 outer). Off-diagonal
// partners share one computation (signs from (-1)^(l1+l2-l)).
#define L0RUN(POS)                                                          \
    F1(POS + 0, 0, 0, 0, 0) F1(POS + 2, 0, 1, 1, 0)                         \
    F1(POS + 4, 0, 2, 2, 0) F1(POS + 6, 0, 3, 3, 0)
#define L1RUN(POS, M)  /* FIs: (0,1)0 (1,0)1 (1,1)2 (1,2)3 (2,1)4 (2,2)5 (2,3)6 (3,2)7 (3,3)8 */ \
    F2(POS + 0,  POS + 2,  +1, 1, 0, 1, M)                                  \
    F1(POS + 4,  1, 1, 1, M)                                                \
    F2(POS + 6,  POS + 8,  +1, 1, 1, 2, M)                                  \
    F1(POS + 10, 1, 2, 2, M)                                                \
    F2(POS + 12, POS + 14, +1, 1, 2, 3, M)                                  \
    F1(POS + 16, 1, 3, 3, M)
#define L2RUN(POS, M)  /* (0,2)0 (1,1)1 (1,2)2 (1,3)3 (2,0)4 (2,1)5 (2,2)6 (2,3)7 (3,1)8 (3,2)9 (3,3)10 */ \
    F2(POS + 0,  POS + 8,  +1, 2, 0, 2, M)                                  \
    F1(POS + 2,  2, 1, 1, M)                                                \
    F2(POS + 4,  POS + 10, -1, 2, 1, 2, M)                                  \
    F2(POS + 6,  POS + 16, +1, 2, 1, 3, M)                                  \
    F1(POS + 12, 2, 2, 2, M)                                                \
    F2(POS + 14, POS + 18, -1, 2, 2, 3, M)                                  \
    F1(POS + 20, 2, 3, 3, M)
#define L3RUN(POS, M)  /* (0,3)0 (1,2)1 (1,3)2 (2,1)3 (2,2)4 (2,3)5 (3,0)6 (3,1)7 (3,2)8 (3,3)9 */ \
    F2(POS + 0,  POS + 12, +1, 3, 0, 3, M)                                  \
    F2(POS + 2,  POS + 6,  +1, 3, 1, 2, M)                                  \
    F2(POS + 4,  POS + 14, -1, 3, 1, 3, M)                                  \
    F1(POS + 8,  3, 2, 2, M)                                                \
    F2(POS + 10, POS + 16, +1, 3, 2, 3, M)                                  \
    F1(POS + 18, 3, 3, 3, M)
#define L4RUN(POS, M)  /* (1,3)0 (2,2)1 (2,3)2 (3,1)3 (3,2)4 (3,3)5 */      \
    F2(POS + 0, POS + 6, +1, 4, 1, 3, M)                                    \
    F1(POS + 2, 4, 2, 2, M)                                                 \
    F2(POS + 4, POS + 8, -1, 4, 2, 3, M)                                    \
    F1(POS + 10, 4, 3, 3, M)
#define L5RUN(POS, M)  /* (2,3)0 (3,2)1 (3,3)2 */                           \
    F2(POS + 0, POS + 2, +1, 5, 2, 3, M)                                    \
    F1(POS + 4, 5, 3, 3, M)

// ---------------------------------------------------------------------------
// Main kernel: one warp per CTA, one thread per batch element; DOUBLE-
// BUFFERED warp-private smem staging. 12 stages (chunks <= 52), alternating
// buffers A/B; one syncwarp per stage; stage-k STGs overlap stage-(k+1)
// compute. Stages split only at m-run boundaries (symmetry pairs intact).
// 16 CTAs/SM = 128-reg budget (only proven spill-free configuration).
// Output layout per element (512 floats):
//   l=0 @0(8)  l=1 @8(54)  l=2 @62(110)  l=3 @172(140)
//   l=4 @312(108)  l=5 @420(66)  l=6 @486(26)
// ---------------------------------------------------------------------------
__global__ void __launch_bounds__(TPB, 16)
cgprod_kernel(const float* __restrict__ x0, const float* __restrict__ x1,
              const float* __restrict__ x2, const float* __restrict__ x3,
              float* __restrict__ out) {
    __shared__ float smA[32 * STRIDE];   // 6912 B
    __shared__ float smB[32 * STRIDE];   // 6912 B  (total 13824 B/CTA)
    const int lane  = threadIdx.x & 31;
    const int wbase = blockIdx.x * 32;
    const int b     = wbase + lane;

    float xr[16], xi[16];
    {
        const float2 v = reinterpret_cast<const float2*>(x0)[b];
        xr[0] = v.x; xi[0] = v.y;
    }
    {
        const float2* p = reinterpret_cast<const float2*>(x1) + (size_t)b * 3;
        #pragma unroll
        for (int k = 0; k < 3; ++k) { const float2 v = p[k]; xr[1 + k] = v.x; xi[1 + k] = v.y; }
    }
    {
        const float2* p = reinterpret_cast<const float2*>(x2) + (size_t)b * 5;
        #pragma unroll
        for (int k = 0; k < 5; ++k) { const float2 v = p[k]; xr[4 + k] = v.x; xi[4 + k] = v.y; }
    }
    {
        const float2* p = reinterpret_cast<const float2*>(x3) + (size_t)b * 7;
        #pragma unroll
        for (int k = 0; k < 7; ++k) { const float2 v = p[k]; xr[9 + k] = v.x; xi[9 + k] = v.y; }
    }

    float* rowA = smA + lane * STRIDE;
    float* rowB = smB + lane * STRIDE;
    float* row;

    // S0 @0 (44): l0 | l1 m=-1 | l1 m=0                       [buf A]
    row = rowA;
    { L0RUN(0) L1RUN(8, -1) L1RUN(26, 0) }
    store_stage<44, 0>(smA, out, wbase, lane);

    // S1 @44 (40): l1 m=1 | l2 m=-2                           [buf B]
    row = rowB;
    { L1RUN(0, 1) L2RUN(18, -2) }
    store_stage<40, 44>(smB, out, wbase, lane);

    // S2 @84 (44): l2 m=-1 | l2 m=0                           [buf A]
    row = rowA;
    { L2RUN(0, -1) L2RUN(22, 0) }
    store_stage<44, 84>(smA, out, wbase, lane);

    // S3 @128 (44): l2 m=1 | l2 m=2                           [buf B]
    row = rowB;
    { L2RUN(0, 1) L2RUN(22, 2) }
    store_stage<44, 128>(smB, out, wbase, lane);

    // S4 @172 (40): l3 m=-3 | l3 m=-2                         [buf A]
    row = rowA;
    { L3RUN(0, -3) L3RUN(20, -2) }
    store_stage<40, 172>(smA, out, wbase, lane);

    // S5 @212 (40): l3 m=-1 | l3 m=0                          [buf B]
    row = rowB;
    { L3RUN(0, -1) L3RUN(20, 0) }
    store_stage<40, 212>(smB, out, wbase, lane);

    // S6 @252 (40): l3 m=1 | l3 m=2                           [buf A]
    row = rowA;
    { L3RUN(0, 1) L3RUN(20, 2) }
    store_stage<40, 252>(smA, out, wbase, lane);

    // S7 @292 (44): l3 m=3 | l4 m=-4 | l4 m=-3                [buf B]
    row = rowB;
    { L3RUN(0, 3) L4RUN(20, -4) L4RUN(32, -3) }
    store_stage<44, 292>(smB, out, wbase, lane);

    // S8 @336 (48): l4 m=-2,-1,0,1                            [buf A]
    row = rowA;
    { L4RUN(0, -2) L4RUN(12, -1) L4RUN(24, 0) L4RUN(36, 1) }
    store_stage<48, 336>(smA, out, wbase, lane);

    // S9 @384 (48): l4 m=2,3,4 | l5 m=-5,-4                   [buf B]
    row = rowB;
    { L4RUN(0, 2) L4RUN(12, 3) L4RUN(24, 4) L5RUN(36, -5) L5RUN(42, -4) }
    store_stage<48, 384>(smB, out, wbase, lane);

    // S10 @432 (48): l5 m=-3..4                               [buf A]
    row = rowA;
    {
        L5RUN(0, -3) L5RUN(6, -2) L5RUN(12, -1) L5RUN(18, 0)
        L5RUN(24, 1) L5RUN(30, 2) L5RUN(36, 3)  L5RUN(42, 4)
    }
    store_stage<48, 432>(smA, out, wbase, lane);

    // S11 @480 (32): l5 m=5 | l6 m=-6..6                      [buf B]
    row = rowB;
    {
        L5RUN(0, 5)
        F1(6, 6, 3, 3, -6)  F1(8, 6, 3, 3, -5)  F1(10, 6, 3, 3, -4)
        F1(12, 6, 3, 3, -3) F1(14, 6, 3, 3, -2) F1(16, 6, 3, 3, -1)
        F1(18, 6, 3, 3,  0) F1(20, 6, 3, 3,  1) F1(22, 6, 3, 3,  2)
        F1(24, 6, 3, 3,  3) F1(26, 6, 3, 3,  4) F1(28, 6, 3, 3,  5)
        F1(30, 6, 3, 3,  6)
    }
    store_stage<32, 480>(smB, out, wbase, lane);
}

extern "C" void kernel_launch(void* const* d_in, const int* in_sizes, int n_in,
                              void* d_out, int out_size) {
    // Defensive: map inputs by element count (all four are distinct).
    const float* xp[4] = {nullptr, nullptr, nullptr, nullptr};
    for (int i = 0; i < n_in && i < 8; ++i) {
        const int s = in_sizes[i];
        if      (s == NB * 2)  xp[0] = (const float*)d_in[i];
        else if (s == NB * 6)  xp[1] = (const float*)d_in[i];
        else if (s == NB * 10) xp[2] = (const float*)d_in[i];
        else if (s == NB * 14) xp[3] = (const float*)d_in[i];
    }
    cgprod_kernel<<<NB / TPB, TPB>>>(xp[0], xp[1], xp[2], xp[3], (float*)d_out);
}

// round 16
// speedup vs baseline: 1.9755x; 1.6850x over previous
#include <cuda_runtime.h>
#include <cstddef>

#define TPB 32               // one warp per CTA
#define STRIDE 66            // floats per smem row; lane*66 % 32 distinct per
                             // half-warp -> conflict-free 64-bit smem ops

static constexpr int NB = 131072;

// ---------------------------------------------------------------------------
// Compile-time Clebsch-Gordan coefficients (Racah formula), double precision,
// evaluated entirely by the compiler (constexpr Newton sqrt).
// ---------------------------------------------------------------------------
__host__ __device__ constexpr double factd(int n) {
    double r = 1.0;
    for (int i = 2; i <= n; ++i) r *= (double)i;
    return r;
}
__host__ __device__ constexpr double csqrt(double x) {
    if (x <= 0.0) return 0.0;
    double g = x > 1.0 ? x : 1.0;
    for (int i = 0; i < 100; ++i) g = 0.5 * (g + x / g);
    return g;
}
__host__ __device__ constexpr int iabs_c(int x) { return x < 0 ? -x : x; }
__host__ __device__ constexpr int imin6(int a, int b, int c, int d, int e, int f) {
    int m = a;
    if (b < m) m = b; if (c < m) m = c; if (d < m) m = d;
    if (e < m) m = e; if (f < m) m = f;
    return m;
}

__host__ __device__ constexpr double cgco(int j1, int m1, int j2, int m2, int j, int m) {
    if (m1 + m2 != m) return 0.0;
    if (j < iabs_c(j1 - j2) || j > j1 + j2) return 0.0;
    if (iabs_c(m) > j || iabs_c(m1) > j1 || iabs_c(m2) > j2) return 0.0;
    double pre = csqrt((2.0 * j + 1.0) * factd(j1 + j2 - j) * factd(j + j1 - j2) *
                       factd(j + j2 - j1) / factd(j1 + j2 + j + 1));
    pre *= csqrt(factd(j + m) * factd(j - m) * factd(j1 + m1) * factd(j1 - m1) *
                 factd(j2 + m2) * factd(j2 - m2));
    double s = 0.0;
    for (int k = 0; k <= j1 + j2 - j; ++k) {
        const int d1 = k;
        const int d2 = j1 + j2 - j - k;
        const int d3 = j1 - m1 - k;
        const int d4 = j2 + m2 - k;
        const int d5 = j - j2 + m1 + k;
        const int d6 = j - j1 - m2 + k;
        if (imin6(d1, d2, d3, d4, d5, d6) < 0) continue;
        const double denom = factd(d1) * factd(d2) * factd(d3) * factd(d4) * factd(d5) * factd(d6);
        s += ((k & 1) ? -1.0 : 1.0) / denom;
    }
    return pre * s;
}

// Register-array offset for input part l (sizes 1,3,5,7 -> offsets 0,1,4,9)
template <int L>
__host__ __device__ constexpr int xoff() { return L == 0 ? 0 : (L == 1 ? 1 : (L == 2 ? 4 : 9)); }

// ---------------------------------------------------------------------------
// Template-unrolled accumulation: sum over m1 for one (l1,l2,l,m) entry set.
// All CG coefficients become FFMA immediates; zero coefficients pruned.
// ---------------------------------------------------------------------------
template <int L1, int L2, int L, int M, int M1>
__device__ __forceinline__ void acc_m1(float& fr, float& fi, const float* xr, const float* xi) {
    constexpr int M2 = M - M1;
    if constexpr (M2 >= -L2 && M2 <= L2) {
        constexpr double Cd = cgco(L1, M1, L2, M2, L, M);
        if constexpr (Cd != 0.0) {
            constexpr float C = (float)Cd;
            const float a = xr[xoff<L1>() + M1 + L1];
            const float b = xi[xoff<L1>() + M1 + L1];
            const float c = xr[xoff<L2>() + M2 + L2];
            const float d = xi[xoff<L2>() + M2 + L2];
            const float pr = fmaf(-b, d, a * c);   // Re(x*y)
            const float pi = fmaf( b, c, a * d);   // Im(x*y)
            fr = fmaf(C, pr, fr);
            fi = fmaf(C, pi, fi);
        }
    }
    if constexpr (M1 < L1) acc_m1<L1, L2, L, M, M1 + 1>(fr, fi, xr, xi);
}

// Single fragment: compute (L1,L2,L,M), one float2 STS at POS (even).
template <int POS, int L, int L1, int L2, int M>
__device__ __forceinline__ void frag1(float* row, const float* xr, const float* xi) {
    float fr = 0.0f, fi = 0.0f;
    acc_m1<L1, L2, L, M, (-L1)>(fr, fi, xr, xi);
    *reinterpret_cast<float2*>(row + POS) = make_float2(fr, fi);
}

// Single fragment with sign: stores SGN * (L1,L2,L,M) at POS. Used when the
// mirror partner lands in a different stage (boundary straddle).
template <int POS, int SGN, int L, int L1, int L2, int M>
__device__ __forceinline__ void frag1s(float* row, const float* xr, const float* xi) {
    float fr = 0.0f, fi = 0.0f;
    acc_m1<L1, L2, L, M, (-L1)>(fr, fi, xr, xi);
    *reinterpret_cast<float2*>(row + POS) =
        make_float2((float)SGN * fr, (float)SGN * fi);
}

// Off-diagonal pair: CG symmetry <l2 m2 l1 m1|l m> = (-1)^(l1+l2-l) <l1 m1 l2 m2|l m>
// and commutativity of the complex product give frag_(l2,l1) = SGN*frag_(l1,l2)
// EXACTLY (bit-identical). Compute once, store both slots.
template <int POS1, int POS2, int SGN, int L, int L1, int L2, int M>
__device__ __forceinline__ void frag2(float* row, const float* xr, const float* xi) {
    float fr = 0.0f, fi = 0.0f;
    acc_m1<L1, L2, L, M, (-L1)>(fr, fi, xr, xi);
    *reinterpret_cast<float2*>(row + POS1) = make_float2(fr, fi);
    *reinterpret_cast<float2*>(row + POS2) =
        make_float2((float)SGN * fr, (float)SGN * fi);
}

// Warp store of one 64-float stage for 32 elements: ALL 32 lanes active,
// division-free affine addressing (lane j holds float2 #j of each element).
// __stcs: output is a 256MB stream (2x L2) never re-read -> evict-first.
template <int STAGE>
__device__ __forceinline__ void store64(const float* smw, float* __restrict__ out,
                                        int wbase, int lane) {
    __syncwarp();
    const float* src = smw + 2 * lane;
    float* dst = out + (size_t)wbase * 512 + STAGE * 64 + 2 * lane;
    #pragma unroll 8
    for (int e = 0; e < 32; ++e) {
        const float2 v = *reinterpret_cast<const float2*>(src + e * STRIDE);
        __stcs(reinterpret_cast<float2*>(dst + (size_t)e * 512), v);
    }
    __syncwarp();
}

#define F1(POS, L, L1, L2, M) frag1<POS, L, L1, L2, M>(row, xr, xi);
#define F1S(POS, S, L, L1, L2, M) frag1s<POS, S, L, L1, L2, M>(row, xr, xi);
#define F2(P1, P2, S, L, L1, L2, M) frag2<P1, P2, S, L, L1, L2, M>(row, xr, xi);

// m-run emitters (same as R13, verified): all fragments of part L at one m,
// run-relative pos POS + 2*FI; gelib order (l1 outer); symmetry-shared.
#define L0RUN(POS)                                                          \
    F1(POS + 0, 0, 0, 0, 0) F1(POS + 2, 0, 1, 1, 0)                         \
    F1(POS + 4, 0, 2, 2, 0) F1(POS + 6, 0, 3, 3, 0)
#define L1RUN(POS, M)                                                       \
    F2(POS + 0,  POS + 2,  +1, 1, 0, 1, M)                                  \
    F1(POS + 4,  1, 1, 1, M)                                                \
    F2(POS + 6,  POS + 8,  +1, 1, 1, 2, M)                                  \
    F1(POS + 10, 1, 2, 2, M)                                                \
    F2(POS + 12, POS + 14, +1, 1, 2, 3, M)                                  \
    F1(POS + 16, 1, 3, 3, M)
#define L2RUN(POS, M)                                                       \
    F2(POS + 0,  POS + 8,  +1, 2, 0, 2, M)                                  \
    F1(POS + 2,  2, 1, 1, M)                                                \
    F2(POS + 4,  POS + 10, -1, 2, 1, 2, M)                                  \
    F2(POS + 6,  POS + 16, +1, 2, 1, 3, M)                                  \
    F1(POS + 12, 2, 2, 2, M)                                                \
    F2(POS + 14, POS + 18, -1, 2, 2, 3, M)                                  \
    F1(POS + 20, 2, 3, 3, M)
#define L3RUN(POS, M)                                                       \
    F2(POS + 0,  POS + 12, +1, 3, 0, 3, M)                                  \
    F2(POS + 2,  POS + 6,  +1, 3, 1, 2, M)                                  \
    F2(POS + 4,  POS + 14, -1, 3, 1, 3, M)                                  \
    F1(POS + 8,  3, 2, 2, M)                                                \
    F2(POS + 10, POS + 16, +1, 3, 2, 3, M)                                  \
    F1(POS + 18, 3, 3, 3, M)
#define L4RUN(POS, M)                                                       \
    F2(POS + 0, POS + 6, +1, 4, 1, 3, M)                                    \
    F1(POS + 2, 4, 2, 2, M)                                                 \
    F2(POS + 4, POS + 8, -1, 4, 2, 3, M)                                    \
    F1(POS + 10, 4, 3, 3, M)
#define L5RUN(POS, M)                                                       \
    F2(POS + 0, POS + 2, +1, 5, 2, 3, M)                                    \
    F1(POS + 4, 5, 3, 3, M)

// ---------------------------------------------------------------------------
// Main kernel: one warp per CTA, one thread per batch element; warp-private
// single-buffer smem staging; 8 stages of EXACTLY 64 output floats (512=8*64)
// -> all-lane division-free stores. Symmetry (frag2) used whenever both
// mirror slots land in one stage; the 3 boundary straddles recompute their
// tiny fragments (~8 CG terms total, <2% extra work).
// Output layout per element (512 floats):
//   l=0 @0(8)  l=1 @8(54)  l=2 @62(110)  l=3 @172(140)
//   l=4 @312(108)  l=5 @420(66)  l=6 @486(26)
// 16 CTAs/SM = 128-reg budget (only proven spill-free configuration).
// ---------------------------------------------------------------------------
__global__ void __launch_bounds__(TPB, 16)
cgprod_kernel(const float* __restrict__ x0, const float* __restrict__ x1,
              const float* __restrict__ x2, const float* __restrict__ x3,
              float* __restrict__ out) {
    __shared__ float sm[32 * STRIDE];   // 8448 B per CTA
    const int lane  = threadIdx.x & 31;
    const int wbase = blockIdx.x * 32;
    const int b     = wbase + lane;

    float xr[16], xi[16];
    {
        const float2 v = reinterpret_cast<const float2*>(x0)[b];
        xr[0] = v.x; xi[0] = v.y;
    }
    {
        const float2* p = reinterpret_cast<const float2*>(x1) + (size_t)b * 3;
        #pragma unroll
        for (int k = 0; k < 3; ++k) { const float2 v = p[k]; xr[1 + k] = v.x; xi[1 + k] = v.y; }
    }
    {
        const float2* p = reinterpret_cast<const float2*>(x2) + (size_t)b * 5;
        #pragma unroll
        for (int k = 0; k < 5; ++k) { const float2 v = p[k]; xr[4 + k] = v.x; xi[4 + k] = v.y; }
    }
    {
        const float2* p = reinterpret_cast<const float2*>(x3) + (size_t)b * 7;
        #pragma unroll
        for (int k = 0; k < 7; ++k) { const float2 v = p[k]; xr[9 + k] = v.x; xi[9 + k] = v.y; }
    }

    float* row = sm + lane * STRIDE;    // this lane's staging row

    // ===== Stage 0 [0,64): l0 | l1 m=-1,0,1 | l2 m=-2 FI0 =====
    {
        L0RUN(0)
        L1RUN(8, -1) L1RUN(26, 0) L1RUN(44, 1)
        F1(62, 2, 0, 2, -2)                      // l2 m=-2 FI0 (0,2); mirror in S1
    }
    store64<0>(sm, out, wbase, lane);

    // ===== Stage 1 [64,128): l2 m=-2 FI1-10 | l2 m=-1 | l2 m=0 =====
    {
        // l2 m=-2 remainder, rel = abs-64 (FI k at rel 2(k-1)):
        F1(0, 2, 1, 1, -2)                       // FI1 diag (1,1)
        F2(2, 8, -1, 2, 1, 2, -2)                // FI2 (1,2) <-> FI5 (2,1)
        F2(4, 14, +1, 2, 1, 3, -2)               // FI3 (1,3) <-> FI8 (3,1)
        F1(6, 2, 0, 2, -2)                       // FI4 (2,0) = +(0,2), recompute (1 term)
        F1(10, 2, 2, 2, -2)                      // FI6 diag (2,2)
        F2(12, 16, -1, 2, 2, 3, -2)              // FI7 (2,3) <-> FI9 (3,2)
        F1(18, 2, 3, 3, -2)                      // FI10 diag (3,3)
        L2RUN(20, -1) L2RUN(42, 0)
    }
    store64<1>(sm, out, wbase, lane);

    // ===== Stage 2 [128,192): l2 m=1,2 | l3 m=-3 =====
    { L2RUN(0, 1) L2RUN(22, 2) L3RUN(44, -3) }
    store64<2>(sm, out, wbase, lane);

    // ===== Stage 3 [192,256): l3 m=-2,-1,0 | l3 m=1 FI0,FI1 =====
    {
        L3RUN(0, -2) L3RUN(20, -1) L3RUN(40, 0)
        F1(60, 3, 0, 3, 1)                       // l3 m=1 FI0 (0,3); mirror in S4
        F1(62, 3, 1, 2, 1)                       // l3 m=1 FI1 (1,2); mirror in S4
    }
    store64<3>(sm, out, wbase, lane);

    // ===== Stage 4 [256,320): l3 m=1 FI2-9 | l3 m=2,3 | l4 m=-4 FI0-3 =====
    {
        // l3 m=1 remainder (FI k at rel 2(k-2)):
        F2(0, 10, -1, 3, 1, 3, 1)                // FI2 (1,3) <-> FI7 (3,1)
        F1(2, 3, 1, 2, 1)                        // FI3 (2,1) = +(1,2), recompute (3 terms)
        F1(4, 3, 2, 2, 1)                        // FI4 diag (2,2)
        F2(6, 12, +1, 3, 2, 3, 1)                // FI5 (2,3) <-> FI8 (3,2)
        F1(8, 3, 0, 3, 1)                        // FI6 (3,0) = +(0,3), recompute (1 term)
        F1(14, 3, 3, 3, 1)                       // FI9 diag (3,3)
        L3RUN(16, 2) L3RUN(36, 3)
        // l4 m=-4 FI0-3 @ rel 56:
        F2(56, 62, +1, 4, 1, 3, -4)              // FI0 (1,3) <-> FI3 (3,1)
        F1(58, 4, 2, 2, -4)                      // FI1 diag (2,2)
        F1(60, 4, 2, 3, -4)                      // FI2 (2,3); mirror in S5
    }
    store64<4>(sm, out, wbase, lane);

    // ===== Stage 5 [320,384): l4 m=-4 FI4,5 | l4 m=-3..1 =====
    {
        F1S(0, -1, 4, 2, 3, -4)                  // FI4 (3,2) = -(2,3), recompute (2 terms)
        F1(2, 4, 3, 3, -4)                       // FI5 diag (3,3)
        L4RUN(4, -3) L4RUN(16, -2) L4RUN(28, -1) L4RUN(40, 0) L4RUN(52, 1)
    }
    store64<5>(sm, out, wbase, lane);

    // ===== Stage 6 [384,448): l4 m=2,3,4 | l5 m=-5..-2 | l5 m=-1 FI0,1 =====
    {
        L4RUN(0, 2) L4RUN(12, 3) L4RUN(24, 4)
        L5RUN(36, -5) L5RUN(42, -4) L5RUN(48, -3) L5RUN(54, -2)
        F2(60, 62, +1, 5, 2, 3, -1)              // l5 m=-1 FI0 <-> FI1, both here
    }
    store64<6>(sm, out, wbase, lane);

    // ===== Stage 7 [448,512): l5 m=-1 FI2 | l5 m=0..5 | l6 all =====
    {
        F1(0, 5, 3, 3, -1)                       // l5 m=-1 FI2 diag (3,3)
        L5RUN(2, 0) L5RUN(8, 1) L5RUN(14, 2) L5RUN(20, 3) L5RUN(26, 4) L5RUN(32, 5)
        F1(38, 6, 3, 3, -6) F1(40, 6, 3, 3, -5) F1(42, 6, 3, 3, -4)
        F1(44, 6, 3, 3, -3) F1(46, 6, 3, 3, -2) F1(48, 6, 3, 3, -1)
        F1(50, 6, 3, 3,  0) F1(52, 6, 3, 3,  1) F1(54, 6, 3, 3,  2)
        F1(56, 6, 3, 3,  3) F1(58, 6, 3, 3,  4) F1(60, 6, 3, 3,  5)
        F1(62, 6, 3, 3,  6)
    }
    store64<7>(sm, out, wbase, lane);
}

extern "C" void kernel_launch(void* const* d_in, const int* in_sizes, int n_in,
                              void* d_out, int out_size) {
    // Defensive: map inputs by element count (all four are distinct).
    const float* xp[4] = {nullptr, nullptr, nullptr, nullptr};
    for (int i = 0; i < n_in && i < 8; ++i) {
        const int s = in_sizes[i];
        if      (s == NB * 2)  xp[0] = (const float*)d_in[i];
        else if (s == NB * 6)  xp[1] = (const float*)d_in[i];
        else if (s == NB * 10) xp[2] = (const float*)d_in[i];
        else if (s == NB * 14) xp[3] = (const float*)d_in[i];
    }
    cgprod_kernel<<<NB / TPB, TPB>>>(xp[0], xp[1], xp[2], xp[3], (float*)d_out);
}